// round 9
// baseline (speedup 1.0000x reference)
#include <cuda_runtime.h>
#include <cstdint>

#define BS 4
#define SL 128
#define DM 512
#define NH 8
#define DP 64

typedef unsigned long long u64;

// ---------------- scratch (device globals; no allocation allowed) ----------------
__device__ int   g_idx[3][SL][SL];        // 0:q 1:k 2:v permutations
__device__ float g_qp[BS*SL*DM];
__device__ float g_kp[BS*SL*DM];
__device__ float g_vp[BS*SL*DM];
__device__ float g_P [BS*NH*SL*SL];       // exp(G - rowmax)
__device__ float g_R [BS*NH*SL*SL];       // 1 / prefix-sum
__device__ float g_eff[BS*SL*DM];

// ---- side streams + events (host objects, created at static-init) ----
struct SideStream {
    cudaStream_t s1, s2;
    cudaEvent_t eb, ep, eg, ed, eu;
    SideStream() {
        cudaStreamCreateWithFlags(&s1, cudaStreamNonBlocking);
        cudaStreamCreateWithFlags(&s2, cudaStreamNonBlocking);
        cudaEventCreateWithFlags(&eb, cudaEventDisableTiming);
        cudaEventCreateWithFlags(&ep, cudaEventDisableTiming);
        cudaEventCreateWithFlags(&eg, cudaEventDisableTiming);
        cudaEventCreateWithFlags(&ed, cudaEventDisableTiming);
        cudaEventCreateWithFlags(&eu, cudaEventDisableTiming);
    }
};
static SideStream g_ss;

// ---------------- packed fp32x2 helpers (sm_103a FFMA2) ----------------
__device__ __forceinline__ u64 pk2(float lo, float hi) {
    u64 r; asm("mov.b64 %0, {%1,%2};" : "=l"(r) : "f"(lo), "f"(hi)); return r;
}
__device__ __forceinline__ void upk2(u64 v, float& lo, float& hi) {
    asm("mov.b64 {%0,%1}, %2;" : "=f"(lo), "=f"(hi) : "l"(v));
}
__device__ __forceinline__ u64 ffma2(u64 a, u64 b, u64 c) {
    u64 d; asm("fma.rn.f32x2 %0, %1, %2, %3;" : "=l"(d) : "l"(a), "l"(b), "l"(c)); return d;
}

// ---------------- threefry2x32 (JAX-compatible) ----------------
__device__ __forceinline__ uint2 tf2x32(uint32_t k0, uint32_t k1, uint32_t x0, uint32_t x1) {
    uint32_t k2 = k0 ^ k1 ^ 0x1BD11BDAu;
    x0 += k0; x1 += k1;
#define TFR(R) { x0 += x1; x1 = (x1 << R) | (x1 >> (32 - R)); x1 ^= x0; }
    TFR(13) TFR(15) TFR(26) TFR(6)
    x0 += k1; x1 += k2 + 1u;
    TFR(17) TFR(29) TFR(16) TFR(24)
    x0 += k2; x1 += k0 + 2u;
    TFR(13) TFR(15) TFR(26) TFR(6)
    x0 += k0; x1 += k1 + 3u;
    TFR(17) TFR(29) TFR(16) TFR(24)
    x0 += k1; x1 += k2 + 4u;
    TFR(13) TFR(15) TFR(26) TFR(6)
    x0 += k2; x1 += k0 + 5u;
#undef TFR
    return make_uint2(x0, x1);
}

// grid (SL, 3), block 128: stable argsort matching jnp.argsort exactly
__global__ void perm_kernel() {
    int t = blockIdx.x, p = blockIdx.y;
    int j = threadIdx.x;
    __shared__ float keys[SL];
    uint2 fk = tf2x32(0u, 42u, 0u, (uint32_t)p);
    float key;
    if (j < t) {
        uint32_t i = (uint32_t)(t * SL + j);
        uint2 r = tf2x32(fk.x, fk.y, 0u, i);
        uint32_t bits = r.x ^ r.y;
        key = __uint_as_float((bits >> 9) | 0x3f800000u) - 1.0f;
    } else {
        key = (float)j + 2.0f;
    }
    keys[j] = key;
    __syncthreads();
    int rank = 0;
    #pragma unroll 8
    for (int jj = 0; jj < SL; jj++) {
        float o = keys[jj];
        rank += (o < key) || (o == key && jj < j);
    }
    g_idx[p][t][rank] = j;
}

// ---------------- 512x512x512 GEMM body (FFMA2 packed): C = A@B + bias --------
__device__ __forceinline__ void gemm512_body(const float* __restrict__ A,
                                             const float* __restrict__ B,
                                             const float* __restrict__ bias,
                                             float* __restrict__ C,
                                             float As[16][68], float Bs[16][68]) {
    int tid = threadIdx.x;
    int bm = blockIdx.y << 6, bn = blockIdx.x << 6;
    int tr = tid >> 4, tc = tid & 15;
    u64 acc2[4][2];
    #pragma unroll
    for (int i = 0; i < 4; i++) { acc2[i][0] = 0ull; acc2[i][1] = 0ull; }

    int lm = tid >> 2, lkq = (tid & 3) << 2;
    int lk = tid >> 4, lnq = (tid & 15) << 2;

    float4 a  = *(const float4*)&A[(bm + lm) * 512 + lkq];
    float4 bb = *(const float4*)&B[lk * 512 + bn + lnq];

    for (int k0 = 0; k0 < 512; k0 += 16) {
        As[lkq + 0][lm] = a.x; As[lkq + 1][lm] = a.y;
        As[lkq + 2][lm] = a.z; As[lkq + 3][lm] = a.w;
        *(float4*)&Bs[lk][lnq] = bb;
        __syncthreads();
        if (k0 + 16 < 512) {
            a  = *(const float4*)&A[(bm + lm) * 512 + k0 + 16 + lkq];
            bb = *(const float4*)&B[(k0 + 16 + lk) * 512 + bn + lnq];
        }
        #pragma unroll
        for (int kk = 0; kk < 16; kk++) {
            float4 av = *(float4*)&As[kk][tr << 2];
            float4 bv = *(float4*)&Bs[kk][tc << 2];
            u64 b01 = pk2(bv.x, bv.y), b23 = pk2(bv.z, bv.w);
            u64 ad;
            ad = pk2(av.x, av.x);
            acc2[0][0] = ffma2(ad, b01, acc2[0][0]);
            acc2[0][1] = ffma2(ad, b23, acc2[0][1]);
            ad = pk2(av.y, av.y);
            acc2[1][0] = ffma2(ad, b01, acc2[1][0]);
            acc2[1][1] = ffma2(ad, b23, acc2[1][1]);
            ad = pk2(av.z, av.z);
            acc2[2][0] = ffma2(ad, b01, acc2[2][0]);
            acc2[2][1] = ffma2(ad, b23, acc2[2][1]);
            ad = pk2(av.w, av.w);
            acc2[3][0] = ffma2(ad, b01, acc2[3][0]);
            acc2[3][1] = ffma2(ad, b23, acc2[3][1]);
        }
        __syncthreads();
    }
    float4 bsv = *(const float4*)&bias[bn + (tc << 2)];
    #pragma unroll
    for (int i = 0; i < 4; i++) {
        float4 o;
        upk2(acc2[i][0], o.x, o.y);
        upk2(acc2[i][1], o.z, o.w);
        o.x += bsv.x; o.y += bsv.y; o.z += bsv.z; o.w += bsv.w;
        *(float4*)&C[(bm + (tr << 2) + i) * 512 + bn + (tc << 2)] = o;
    }
}

// grid (8,8,2): z selects q/k projection (critical path)
__global__ void gemm_qk_kernel(const float* __restrict__ q, const float* __restrict__ k,
                               const float* __restrict__ wq, const float* __restrict__ wk,
                               const float* __restrict__ bq, const float* __restrict__ bk) {
    __shared__ float As[16][68], Bs[16][68];
    const float *A, *B, *bias; float* C;
    if (blockIdx.z == 0) { A = q; B = wq; bias = bq; C = g_qp; }
    else                 { A = k; B = wk; bias = bk; C = g_kp; }
    gemm512_body(A, B, bias, C, As, Bs);
}

// grid (8,8): v projection (side branch)
__global__ void gemm_v_kernel(const float* __restrict__ v, const float* __restrict__ wv,
                              const float* __restrict__ bv) {
    __shared__ float As[16][68], Bs[16][68];
    gemm512_body(v, wv, bv, g_vp, As, Bs);
}

// grid (8,8): final dense: out = g_eff @ wd + bd
__global__ void gemm_out_kernel(const float* __restrict__ wd, const float* __restrict__ bd,
                                float* __restrict__ out) {
    __shared__ float As[16][68], Bs[16][68];
    gemm512_body(g_eff, wd, bd, out, As, Bs);
}

// ---------------- G = Q K^T /8 per (b,h); P = exp(G-max); R = 1/prefix-sum ------
// grid (16 rowchunks, NH, BS) = 512 blocks, block 256. Each block: 8 rows x 128 cols.
__global__ void gp_kernel() {
    __shared__ float ks_s[128][68];
    __shared__ float Gs[8][128];
    int rc = blockIdx.x, h = blockIdx.y, b = blockIdx.z;
    int i0 = rc << 3;
    int tid = threadIdx.x;
    int j = tid & 127;
    int ihalf = tid >> 7;

    #pragma unroll
    for (int u = 0; u < 8; u++) {
        int lin = tid + u * 256;
        int j2 = lin >> 4;
        int dq = (lin & 15) << 2;
        float4 kv = *(const float4*)&g_kp[((b * SL + j2) << 9) + (h << 6) + dq];
        *(float4*)&ks_s[j2][dq] = kv;
    }
    __syncthreads();

    float acc[4];
    #pragma unroll
    for (int r = 0; r < 4; r++) acc[r] = 0.f;
    const float* qbase = g_qp + ((b * SL + i0) << 9) + (h << 6);
    #pragma unroll
    for (int d4 = 0; d4 < 16; d4++) {
        float4 kv = *(const float4*)&ks_s[j][d4 << 2];
        #pragma unroll
        for (int r = 0; r < 4; r++) {
            float4 qv = __ldg((const float4*)&qbase[(((ihalf << 2) + r) << 9) + (d4 << 2)]);
            acc[r] += qv.x * kv.x + qv.y * kv.y + qv.z * kv.z + qv.w * kv.w;
        }
    }
    #pragma unroll
    for (int r = 0; r < 4; r++) Gs[(ihalf << 2) + r][j] = acc[r] * 0.125f;
    __syncthreads();

    int w = tid >> 5, lane = tid & 31;
    {
        int i = w;
        float4 g = *(float4*)&Gs[i][lane << 2];
        float m = fmaxf(fmaxf(g.x, g.y), fmaxf(g.z, g.w));
        #pragma unroll
        for (int off = 16; off; off >>= 1) m = fmaxf(m, __shfl_xor_sync(0xffffffffu, m, off));
        float e0 = __expf(g.x - m), e1 = __expf(g.y - m);
        float e2 = __expf(g.z - m), e3 = __expf(g.w - m);
        int rowbase = ((b * NH + h) * SL + i0 + i) * SL;
        *(float4*)&g_P[rowbase + (lane << 2)] = make_float4(e0, e1, e2, e3);
        float s1 = e0 + e1, s2 = s1 + e2, s3 = s2 + e3;
        float tot = s3, sc = tot;
        #pragma unroll
        for (int off = 1; off < 32; off <<= 1) {
            float o = __shfl_up_sync(0xffffffffu, sc, off);
            if (lane >= off) sc += o;
        }
        float excl = sc - tot;
        *(float4*)&g_R[rowbase + (lane << 2)] =
            make_float4(1.0f / (excl + e0), 1.0f / (excl + s1),
                        1.0f / (excl + s2), 1.0f / (excl + s3));
    }
}

// ---------------- attn uniform region: rows q > t (no dependencies!) ----------
// attn[b,t,h,q,k] = (k<=t) ? 1/(t+1) : 0   for q > t.  ~128 MB of pure stores.
// grid (SL, NH, BS), block 256
__global__ void __launch_bounds__(256, 6) attn_uniform_kernel(float* __restrict__ attn) {
    int t = blockIdx.x, h = blockIdx.y, b = blockIdx.z;
    int tid = threadIdx.x;
    int lane = tid & 31, w = tid >> 5;
    int k0 = lane << 2;
    float uval = 1.0f / (float)(t + 1);
    float4 uv;
    uv.x = (k0     <= t) ? uval : 0.f;
    uv.y = (k0 + 1 <= t) ? uval : 0.f;
    uv.z = (k0 + 2 <= t) ? uval : 0.f;
    uv.w = (k0 + 3 <= t) ? uval : 0.f;
    float* base = attn + (((size_t)((b * SL + t) * NH + h)) << 14);
    for (int q = t + 1 + w; q < SL; q += 8) {
        __stcs((float4*)&base[q * SL + k0], uv);
    }
}

// ---------------- attn gathered region: rows q <= t (needs gp + perm) ----------
// grid (SL, NH, BS), block 256 = 8 warps; warp w does q rows w, w+8, ... in pairs
__global__ void __launch_bounds__(256, 6) attn_gather_kernel(float* __restrict__ attn) {
    int t = blockIdx.x, h = blockIdx.y, b = blockIdx.z;
    __shared__ int idxk_s[SL];
    __shared__ int idxq_s[SL];
    __shared__ float pbuf[8][2][SL];
    int tid = threadIdx.x;
    if (tid < SL) {
        idxk_s[tid] = g_idx[1][t][tid];
        idxq_s[tid] = g_idx[0][t][tid];
    }
    __syncthreads();
    float* base = attn + (((size_t)((b * SL + t) * NH + h)) << 14);
    const float* Pbh = g_P + ((size_t)(b * NH + h) << 14);
    const float* Rbh = g_R + ((size_t)(b * NH + h) << 14);
    int lane = tid & 31, w = tid >> 5;
    int k0 = lane << 2;
    int  j0 = idxk_s[k0], j1 = idxk_s[k0 + 1], j2 = idxk_s[k0 + 2], j3 = idxk_s[k0 + 3];
    bool p0 = (k0 <= t), p1 = (k0 + 1 <= t), p2 = (k0 + 2 <= t), p3 = (k0 + 3 <= t);

    for (int qq = w; qq <= t; qq += 16) {
        int q2 = qq + 8;
        bool have2 = (q2 <= t);
        int iq0 = idxq_s[qq];
        float r0 = __ldg(&Rbh[iq0 * SL + t]);
        float4 P0 = __ldg((const float4*)&Pbh[iq0 * SL + k0]);
        float r1 = 0.f; float4 P1;
        if (have2) {
            int iq1 = idxq_s[q2];
            r1 = __ldg(&Rbh[iq1 * SL + t]);
            P1 = __ldg((const float4*)&Pbh[iq1 * SL + k0]);
        }
        *(float4*)&pbuf[w][0][k0] = P0;
        if (have2) *(float4*)&pbuf[w][1][k0] = P1;
        __syncwarp();
        const float* pa = pbuf[w][0];
        float4 v0;
        v0.x = p0 ? pa[j0] * r0 : 0.f;
        v0.y = p1 ? pa[j1] * r0 : 0.f;
        v0.z = p2 ? pa[j2] * r0 : 0.f;
        v0.w = p3 ? pa[j3] * r0 : 0.f;
        __stcs((float4*)&base[qq * SL + k0], v0);
        if (have2) {
            const float* pb = pbuf[w][1];
            float4 v1;
            v1.x = p0 ? pb[j0] * r1 : 0.f;
            v1.y = p1 ? pb[j1] * r1 : 0.f;
            v1.z = p2 ? pb[j2] * r1 : 0.f;
            v1.w = p3 ? pb[j3] * r1 : 0.f;
            __stcs((float4*)&base[q2 * SL + k0], v1);
        }
        __syncwarp();
    }
}

// ---------------- eff[b,t,:] = diag ctx row, permutation-inverted ----------------
__global__ void eff_kernel() {
    int t = blockIdx.x, b = blockIdx.y;
    int tid = threadIdx.x;
    __shared__ int inv_s[SL];
    __shared__ float ws[NH][SL];
    if (tid < SL) inv_s[g_idx[2][t][tid]] = tid;
    __syncthreads();
    for (int idx = tid; idx < NH * SL; idx += 256) {
        int h = idx >> 7, j = idx & 127;
        int k = inv_s[j];
        float val = 0.f;
        if (k <= t) {
            int jj = g_idx[1][t][k];
            int rb = ((b * NH + h) * SL + t) * SL;
            val = g_P[rb + jj] * g_R[rb + t];
        }
        ws[h][j] = val;
    }
    __syncthreads();
    int h0 = tid >> 6;
    int c1 = tid + 256, h1 = c1 >> 6;
    const float* Vb = g_vp + ((size_t)(b * SL) << 9);
    float a0 = 0.f, a1 = 0.f, b0 = 0.f, b1 = 0.f;
    float c0a = 0.f, c1a = 0.f, d0a = 0.f, d1a = 0.f;
    int j = 0;
    for (; j + 3 <= t; j += 4) {
        const float* r0 = Vb + ((size_t)(j    ) << 9);
        const float* r1 = Vb + ((size_t)(j + 1) << 9);
        const float* r2 = Vb + ((size_t)(j + 2) << 9);
        const float* r3 = Vb + ((size_t)(j + 3) << 9);
        a0  += ws[h0][j    ] * __ldg(&r0[tid]);
        a1  += ws[h1][j    ] * __ldg(&r0[c1]);
        b0  += ws[h0][j + 1] * __ldg(&r1[tid]);
        b1  += ws[h1][j + 1] * __ldg(&r1[c1]);
        c0a += ws[h0][j + 2] * __ldg(&r2[tid]);
        c1a += ws[h1][j + 2] * __ldg(&r2[c1]);
        d0a += ws[h0][j + 3] * __ldg(&r3[tid]);
        d1a += ws[h1][j + 3] * __ldg(&r3[c1]);
    }
    for (; j <= t; j++) {
        const float* r0 = Vb + ((size_t)j << 9);
        a0 += ws[h0][j] * __ldg(&r0[tid]);
        a1 += ws[h1][j] * __ldg(&r0[c1]);
    }
    size_t ob = (size_t)(b * SL + t) << 9;
    g_eff[ob + tid] = (a0 + b0) + (c0a + d0a);
    g_eff[ob + c1]  = (a1 + b1) + (c1a + d1a);
}

// ---------------- launch (fork/join DAG for graph capture) ----------------
//   s2: attn_uniform (no deps, starts immediately, ~26us of stores)
//   0 : gemm_qk -> gp -(eg)-> (wait ep) attn_gather -> (wait ed, eu)
//   s1: perm -(ep)-> gemm_v -> (wait eg) eff -> gemm_out -(ed)
extern "C" void kernel_launch(void* const* d_in, const int* in_sizes, int n_in,
                              void* d_out, int out_size) {
    const float* q  = (const float*)d_in[0];
    const float* k  = (const float*)d_in[1];
    const float* v  = (const float*)d_in[2];
    // d_in[3] = mask (recomputed analytically, unused)
    const float* wq = (const float*)d_in[4];
    const float* bq = (const float*)d_in[5];
    const float* wk = (const float*)d_in[6];
    const float* bk = (const float*)d_in[7];
    const float* wv = (const float*)d_in[8];
    const float* bv = (const float*)d_in[9];
    const float* wd = (const float*)d_in[10];
    const float* bd = (const float*)d_in[11];

    float* out  = (float*)d_out;                 // (BS,SL,DM)
    float* attn = out + (size_t)BS * SL * DM;    // (BS,SL,NH,SL,SL)

    cudaStream_t s1 = g_ss.s1, s2 = g_ss.s2;

    // fork
    cudaEventRecord(g_ss.eb, 0);
    cudaStreamWaitEvent(s1, g_ss.eb, 0);
    cudaStreamWaitEvent(s2, g_ss.eb, 0);

    // s2: dependency-free half of the big output — starts at t=0
    attn_uniform_kernel<<<dim3(SL, NH, BS), 256, 0, s2>>>(attn);
    cudaEventRecord(g_ss.eu, s2);

    // s1: perm + v-projection
    perm_kernel<<<dim3(SL, 3, 1), 128, 0, s1>>>();
    cudaEventRecord(g_ss.ep, s1);
    gemm_v_kernel<<<dim3(8, 8, 1), 256, 0, s1>>>(v, wv, bv);

    // main: q/k projections -> gram/softmax tables
    gemm_qk_kernel<<<dim3(8, 8, 2), 256>>>(q, k, wq, wk, bq, bk);
    gp_kernel<<<dim3(16, NH, BS), 256>>>();
    cudaEventRecord(g_ss.eg, 0);

    // s1 continues: eff -> dense
    cudaStreamWaitEvent(s1, g_ss.eg, 0);
    eff_kernel<<<dim3(SL, BS), 256, 0, s1>>>();
    gemm_out_kernel<<<dim3(8, 8, 1), 256, 0, s1>>>(wd, bd, out);
    cudaEventRecord(g_ss.ed, s1);

    // main: gathered half of attn (needs gp + perm)
    cudaStreamWaitEvent(0, g_ss.ep, 0);
    attn_gather_kernel<<<dim3(SL, NH, BS), 256>>>(attn);

    // join
    cudaStreamWaitEvent(0, g_ss.ed, 0);
    cudaStreamWaitEvent(0, g_ss.eu, 0);
}

// round 10
// speedup vs baseline: 1.3326x; 1.3326x over previous
#include <cuda_runtime.h>
#include <cstdint>

#define BS 4
#define SL 128
#define DM 512
#define NH 8
#define DP 64

typedef unsigned long long u64;

// ---------------- scratch (device globals; no allocation allowed) ----------------
__device__ int   g_idx[3][SL][SL];        // 0:q 1:k 2:v permutations
__device__ float g_qp[BS*SL*DM];
__device__ float g_kp[BS*SL*DM];
__device__ float g_vp[BS*SL*DM];
__device__ float g_P [BS*NH*SL*SL];       // exp(G - rowmax)
__device__ float g_R [BS*NH*SL*SL];       // 1 / prefix-sum
__device__ float g_eff[BS*SL*DM];

// ---- side stream + events (host objects, created at static-init) ----
struct SideStream {
    cudaStream_t s1;
    cudaEvent_t eg, ed;
    SideStream() {
        cudaStreamCreateWithFlags(&s1, cudaStreamNonBlocking);
        cudaEventCreateWithFlags(&eg, cudaEventDisableTiming);
        cudaEventCreateWithFlags(&ed, cudaEventDisableTiming);
    }
};
static SideStream g_ss;

// ---------------- packed fp32x2 helpers (sm_103a FFMA2) ----------------
__device__ __forceinline__ u64 pk2(float lo, float hi) {
    u64 r; asm("mov.b64 %0, {%1,%2};" : "=l"(r) : "f"(lo), "f"(hi)); return r;
}
__device__ __forceinline__ void upk2(u64 v, float& lo, float& hi) {
    asm("mov.b64 {%0,%1}, %2;" : "=f"(lo), "=f"(hi) : "l"(v));
}
__device__ __forceinline__ u64 ffma2(u64 a, u64 b, u64 c) {
    u64 d; asm("fma.rn.f32x2 %0, %1, %2, %3;" : "=l"(d) : "l"(a), "l"(b), "l"(c)); return d;
}

// ---------------- threefry2x32 (JAX-compatible) ----------------
__device__ __forceinline__ uint2 tf2x32(uint32_t k0, uint32_t k1, uint32_t x0, uint32_t x1) {
    uint32_t k2 = k0 ^ k1 ^ 0x1BD11BDAu;
    x0 += k0; x1 += k1;
#define TFR(R) { x0 += x1; x1 = (x1 << R) | (x1 >> (32 - R)); x1 ^= x0; }
    TFR(13) TFR(15) TFR(26) TFR(6)
    x0 += k1; x1 += k2 + 1u;
    TFR(17) TFR(29) TFR(16) TFR(24)
    x0 += k2; x1 += k0 + 2u;
    TFR(13) TFR(15) TFR(26) TFR(6)
    x0 += k0; x1 += k1 + 3u;
    TFR(17) TFR(29) TFR(16) TFR(24)
    x0 += k1; x1 += k2 + 4u;
    TFR(13) TFR(15) TFR(26) TFR(6)
    x0 += k2; x1 += k0 + 5u;
#undef TFR
    return make_uint2(x0, x1);
}

// ---------------- 512x512x512 GEMM body (FFMA2 packed): C = A@B + bias --------
__device__ __forceinline__ void gemm512_body(const float* __restrict__ A,
                                             const float* __restrict__ B,
                                             const float* __restrict__ bias,
                                             float* __restrict__ C,
                                             float As[16][68], float Bs[16][68]) {
    int tid = threadIdx.x;
    int bm = blockIdx.y << 6, bn = blockIdx.x << 6;
    int tr = tid >> 4, tc = tid & 15;
    u64 acc2[4][2];
    #pragma unroll
    for (int i = 0; i < 4; i++) { acc2[i][0] = 0ull; acc2[i][1] = 0ull; }

    int lm = tid >> 2, lkq = (tid & 3) << 2;
    int lk = tid >> 4, lnq = (tid & 15) << 2;

    float4 a  = *(const float4*)&A[(bm + lm) * 512 + lkq];
    float4 bb = *(const float4*)&B[lk * 512 + bn + lnq];

    for (int k0 = 0; k0 < 512; k0 += 16) {
        As[lkq + 0][lm] = a.x; As[lkq + 1][lm] = a.y;
        As[lkq + 2][lm] = a.z; As[lkq + 3][lm] = a.w;
        *(float4*)&Bs[lk][lnq] = bb;
        __syncthreads();
        if (k0 + 16 < 512) {
            a  = *(const float4*)&A[(bm + lm) * 512 + k0 + 16 + lkq];
            bb = *(const float4*)&B[(k0 + 16 + lk) * 512 + bn + lnq];
        }
        #pragma unroll
        for (int kk = 0; kk < 16; kk++) {
            float4 av = *(float4*)&As[kk][tr << 2];
            float4 bv = *(float4*)&Bs[kk][tc << 2];
            u64 b01 = pk2(bv.x, bv.y), b23 = pk2(bv.z, bv.w);
            u64 ad;
            ad = pk2(av.x, av.x);
            acc2[0][0] = ffma2(ad, b01, acc2[0][0]);
            acc2[0][1] = ffma2(ad, b23, acc2[0][1]);
            ad = pk2(av.y, av.y);
            acc2[1][0] = ffma2(ad, b01, acc2[1][0]);
            acc2[1][1] = ffma2(ad, b23, acc2[1][1]);
            ad = pk2(av.z, av.z);
            acc2[2][0] = ffma2(ad, b01, acc2[2][0]);
            acc2[2][1] = ffma2(ad, b23, acc2[2][1]);
            ad = pk2(av.w, av.w);
            acc2[3][0] = ffma2(ad, b01, acc2[3][0]);
            acc2[3][1] = ffma2(ad, b23, acc2[3][1]);
        }
        __syncthreads();
    }
    float4 bsv = *(const float4*)&bias[bn + (tc << 2)];
    #pragma unroll
    for (int i = 0; i < 4; i++) {
        float4 o;
        upk2(acc2[i][0], o.x, o.y);
        upk2(acc2[i][1], o.z, o.w);
        o.x += bsv.x; o.y += bsv.y; o.z += bsv.z; o.w += bsv.w;
        *(float4*)&C[(bm + (tr << 2) + i) * 512 + bn + (tc << 2)] = o;
    }
}

// ---------------- fused: q/k/v projections (z=0..2) + all 3 perms (z=3) --------
// grid (8,8,4), block 256
__global__ void fused_proj_perm_kernel(
        const float* __restrict__ q, const float* __restrict__ k,
        const float* __restrict__ v,
        const float* __restrict__ wq, const float* __restrict__ wk,
        const float* __restrict__ wv,
        const float* __restrict__ bq, const float* __restrict__ bk,
        const float* __restrict__ bv) {
    __shared__ float As[16][68], Bs[16][68];
    __shared__ float keys[2][SL];
    int z = blockIdx.z;
    if (z < 3) {
        const float *A, *B, *bias; float* C;
        if (z == 0)      { A = q; B = wq; bias = bq; C = g_qp; }
        else if (z == 1) { A = k; B = wk; bias = bk; C = g_kp; }
        else             { A = v; B = wv; bias = bv; C = g_vp; }
        gemm512_body(A, B, bias, C, As, Bs);
        return;
    }
    // perm branch: 64 blocks, each does 2 sort-rows per perm, 3 perms
    int id = blockIdx.y * 8 + blockIdx.x;        // 0..63
    int tid = threadIdx.x;
    int half = tid >> 7, j = tid & 127;
    int t = id * 2 + half;                       // 0..127
    for (int p = 0; p < 3; p++) {
        uint2 fk = tf2x32(0u, 42u, 0u, (uint32_t)p);
        float key;
        if (j < t) {
            // jax_threefry_partitionable counter-mode bits: w0 ^ w1 of tf(key, 0, i)
            uint32_t i = (uint32_t)(t * SL + j);
            uint2 r = tf2x32(fk.x, fk.y, 0u, i);
            uint32_t bits = r.x ^ r.y;
            key = __uint_as_float((bits >> 9) | 0x3f800000u) - 1.0f;
        } else {
            key = (float)j + 2.0f;
        }
        keys[half][j] = key;
        __syncthreads();
        int rank = 0;
        #pragma unroll 8
        for (int jj = 0; jj < SL; jj++) {
            float o = keys[half][jj];
            rank += (o < key) || (o == key && jj < j);
        }
        g_idx[p][t][rank] = j;
        __syncthreads();
    }
}

// grid (8,8): final dense: out = g_eff @ wd + bd
__global__ void gemm_out_kernel(const float* __restrict__ wd, const float* __restrict__ bd,
                                float* __restrict__ out) {
    __shared__ float As[16][68], Bs[16][68];
    gemm512_body(g_eff, wd, bd, out, As, Bs);
}

// ---------------- G = Q K^T /8 per (b,h); P = exp(G-max); R = 1/prefix-sum ------
// grid (16 rowchunks, NH, BS) = 512 blocks, block 256. Each block: 8 rows x 128 cols.
// K tile stored TRANSPOSED in smem with stride 129 (odd mod 32 -> conflict-free).
__global__ void gp_kernel() {
    __shared__ float ksT[64][129];    // [d][j]
    __shared__ float Gs[8][128];
    int rc = blockIdx.x, h = blockIdx.y, b = blockIdx.z;
    int i0 = rc << 3;
    int tid = threadIdx.x;
    int j = tid & 127;
    int ihalf = tid >> 7;

    // load K tile (128 rows x 64 d) -> transposed smem
    #pragma unroll
    for (int u = 0; u < 8; u++) {
        int lin = tid + u * 256;
        int j2 = lin >> 4;
        int dq = (lin & 15) << 2;
        float4 kv = *(const float4*)&g_kp[((b * SL + j2) << 9) + (h << 6) + dq];
        ksT[dq + 0][j2] = kv.x;
        ksT[dq + 1][j2] = kv.y;
        ksT[dq + 2][j2] = kv.z;
        ksT[dq + 3][j2] = kv.w;
    }
    __syncthreads();

    float acc[4];
    #pragma unroll
    for (int r = 0; r < 4; r++) acc[r] = 0.f;
    const float* qbase = g_qp + ((b * SL + i0) << 9) + (h << 6);
    #pragma unroll
    for (int d4 = 0; d4 < 16; d4++) {
        float k0v = ksT[(d4 << 2) + 0][j];
        float k1v = ksT[(d4 << 2) + 1][j];
        float k2v = ksT[(d4 << 2) + 2][j];
        float k3v = ksT[(d4 << 2) + 3][j];
        #pragma unroll
        for (int r = 0; r < 4; r++) {
            float4 qv = __ldg((const float4*)&qbase[(((ihalf << 2) + r) << 9) + (d4 << 2)]);
            acc[r] += qv.x * k0v + qv.y * k1v + qv.z * k2v + qv.w * k3v;
        }
    }
    #pragma unroll
    for (int r = 0; r < 4; r++) Gs[(ihalf << 2) + r][j] = acc[r] * 0.125f;
    __syncthreads();

    int w = tid >> 5, lane = tid & 31;
    {
        int i = w;
        float4 g = *(float4*)&Gs[i][lane << 2];
        float m = fmaxf(fmaxf(g.x, g.y), fmaxf(g.z, g.w));
        #pragma unroll
        for (int off = 16; off; off >>= 1) m = fmaxf(m, __shfl_xor_sync(0xffffffffu, m, off));
        float e0 = __expf(g.x - m), e1 = __expf(g.y - m);
        float e2 = __expf(g.z - m), e3 = __expf(g.w - m);
        int rowbase = ((b * NH + h) * SL + i0 + i) * SL;
        *(float4*)&g_P[rowbase + (lane << 2)] = make_float4(e0, e1, e2, e3);
        float s1 = e0 + e1, s2 = s1 + e2, s3 = s2 + e3;
        float tot = s3, sc = tot;
        #pragma unroll
        for (int off = 1; off < 32; off <<= 1) {
            float o = __shfl_up_sync(0xffffffffu, sc, off);
            if (lane >= off) sc += o;
        }
        float excl = sc - tot;
        *(float4*)&g_R[rowbase + (lane << 2)] =
            make_float4(1.0f / (excl + e0), 1.0f / (excl + s1),
                        1.0f / (excl + s2), 1.0f / (excl + s3));
    }
}

// ---------------- big writer: attn[b,t,h,q,k] (256 MB) ----------------
// grid (SL, NH, BS), block 256 = 8 warps; warp w does q rows w, w+8, ... in pairs
__global__ void __launch_bounds__(256, 6) attn_write_kernel(float* __restrict__ attn) {
    int t = blockIdx.x, h = blockIdx.y, b = blockIdx.z;
    __shared__ int idxk_s[SL];
    __shared__ int idxq_s[SL];
    __shared__ float pbuf[8][2][SL];
    int tid = threadIdx.x;
    if (tid < SL) {
        idxk_s[tid] = g_idx[1][t][tid];
        idxq_s[tid] = g_idx[0][t][tid];
    }
    __syncthreads();
    float uval = 1.0f / (float)(t + 1);
    float* base = attn + (((size_t)((b * SL + t) * NH + h)) << 14);
    const float* Pbh = g_P + ((size_t)(b * NH + h) << 14);
    const float* Rbh = g_R + ((size_t)(b * NH + h) << 14);
    int lane = tid & 31, w = tid >> 5;
    int k0 = lane << 2;
    int  j0 = idxk_s[k0], j1 = idxk_s[k0 + 1], j2 = idxk_s[k0 + 2], j3 = idxk_s[k0 + 3];
    bool p0 = (k0 <= t), p1 = (k0 + 1 <= t), p2 = (k0 + 2 <= t), p3 = (k0 + 3 <= t);

    // gathered region: rows == w (mod 8), <= t, two per iteration
    for (int qq = w; qq <= t; qq += 16) {
        int q2 = qq + 8;
        bool have2 = (q2 <= t);
        int iq0 = idxq_s[qq];
        float r0 = __ldg(&Rbh[iq0 * SL + t]);
        float4 P0 = __ldg((const float4*)&Pbh[iq0 * SL + k0]);
        float r1 = 0.f; float4 P1;
        if (have2) {
            int iq1 = idxq_s[q2];
            r1 = __ldg(&Rbh[iq1 * SL + t]);
            P1 = __ldg((const float4*)&Pbh[iq1 * SL + k0]);
        }
        *(float4*)&pbuf[w][0][k0] = P0;
        if (have2) *(float4*)&pbuf[w][1][k0] = P1;
        __syncwarp();
        const float* pa = pbuf[w][0];
        float4 v0;
        v0.x = p0 ? pa[j0] * r0 : 0.f;
        v0.y = p1 ? pa[j1] * r0 : 0.f;
        v0.z = p2 ? pa[j2] * r0 : 0.f;
        v0.w = p3 ? pa[j3] * r0 : 0.f;
        __stcs((float4*)&base[qq * SL + k0], v0);
        if (have2) {
            const float* pb = pbuf[w][1];
            float4 v1;
            v1.x = p0 ? pb[j0] * r1 : 0.f;
            v1.y = p1 ? pb[j1] * r1 : 0.f;
            v1.z = p2 ? pb[j2] * r1 : 0.f;
            v1.w = p3 ? pb[j3] * r1 : 0.f;
            __stcs((float4*)&base[q2 * SL + k0], v1);
        }
        __syncwarp();
    }
    // uniform region: rows == w (mod 8), > t
    float4 uv;
    uv.x = p0 ? uval : 0.f;
    uv.y = p1 ? uval : 0.f;
    uv.z = p2 ? uval : 0.f;
    uv.w = p3 ? uval : 0.f;
    int u0 = (w > t) ? w : (w + ((t - w) / 8 + 1) * 8);
    for (int q2 = u0; q2 < SL; q2 += 8) {
        __stcs((float4*)&base[q2 * SL + k0], uv);
    }
}

// ---------------- eff[b,t,:] = diag ctx row, permutation-inverted ----------------
// grid (SL, BS), block 256; sequential coalesced V reads via inverse perm.
__global__ void eff_kernel() {
    int t = blockIdx.x, b = blockIdx.y;
    int tid = threadIdx.x;
    __shared__ int inv_s[SL];
    __shared__ float ws[NH][SL];
    if (tid < SL) inv_s[g_idx[2][t][tid]] = tid;
    __syncthreads();
    for (int idx = tid; idx < NH * SL; idx += 256) {
        int h = idx >> 7, j = idx & 127;
        int k = inv_s[j];
        float val = 0.f;
        if (k <= t) {
            int jj = g_idx[1][t][k];
            int rb = ((b * NH + h) * SL + t) * SL;
            val = g_P[rb + jj] * g_R[rb + t];
        }
        ws[h][j] = val;
    }
    __syncthreads();
    int h0 = tid >> 6;
    int c1 = tid + 256, h1 = c1 >> 6;
    const float* Vb = g_vp + ((size_t)(b * SL) << 9);
    float a0 = 0.f, a1 = 0.f, b0 = 0.f, b1 = 0.f;
    float c0a = 0.f, c1a = 0.f, d0a = 0.f, d1a = 0.f;
    int j = 0;
    for (; j + 3 <= t; j += 4) {
        const float* r0 = Vb + ((size_t)(j    ) << 9);
        const float* r1 = Vb + ((size_t)(j + 1) << 9);
        const float* r2 = Vb + ((size_t)(j + 2) << 9);
        const float* r3 = Vb + ((size_t)(j + 3) << 9);
        a0  += ws[h0][j    ] * __ldg(&r0[tid]);
        a1  += ws[h1][j    ] * __ldg(&r0[c1]);
        b0  += ws[h0][j + 1] * __ldg(&r1[tid]);
        b1  += ws[h1][j + 1] * __ldg(&r1[c1]);
        c0a += ws[h0][j + 2] * __ldg(&r2[tid]);
        c1a += ws[h1][j + 2] * __ldg(&r2[c1]);
        d0a += ws[h0][j + 3] * __ldg(&r3[tid]);
        d1a += ws[h1][j + 3] * __ldg(&r3[c1]);
    }
    for (; j <= t; j++) {
        const float* r0 = Vb + ((size_t)j << 9);
        a0 += ws[h0][j] * __ldg(&r0[tid]);
        a1 += ws[h1][j] * __ldg(&r0[c1]);
    }
    size_t ob = (size_t)(b * SL + t) << 9;
    g_eff[ob + tid] = (a0 + b0) + (c0a + d0a);
    g_eff[ob + c1]  = (a1 + b1) + (c1a + d1a);
}

// ---------------- launch: 5 kernel nodes ----------------
//   0 : fused_proj_perm -> gp -(eg)-> attn_write -> (wait ed)
//   s1: (wait eg) eff -> gemm_out -(ed)
extern "C" void kernel_launch(void* const* d_in, const int* in_sizes, int n_in,
                              void* d_out, int out_size) {
    const float* q  = (const float*)d_in[0];
    const float* k  = (const float*)d_in[1];
    const float* v  = (const float*)d_in[2];
    // d_in[3] = mask (recomputed analytically, unused)
    const float* wq = (const float*)d_in[4];
    const float* bq = (const float*)d_in[5];
    const float* wk = (const float*)d_in[6];
    const float* bk = (const float*)d_in[7];
    const float* wv = (const float*)d_in[8];
    const float* bv = (const float*)d_in[9];
    const float* wd = (const float*)d_in[10];
    const float* bd = (const float*)d_in[11];

    float* out  = (float*)d_out;                 // (BS,SL,DM)
    float* attn = out + (size_t)BS * SL * DM;    // (BS,SL,NH,SL,SL)

    cudaStream_t s1 = g_ss.s1;

    // main: fused projections+perms -> gram/softmax tables
    fused_proj_perm_kernel<<<dim3(8, 8, 4), 256>>>(q, k, v, wq, wk, wv, bq, bk, bv);
    gp_kernel<<<dim3(16, NH, BS), 256>>>();
    cudaEventRecord(g_ss.eg, 0);

    // side: eff -> dense (overlaps attn_write)
    cudaStreamWaitEvent(s1, g_ss.eg, 0);
    eff_kernel<<<dim3(SL, BS), 256, 0, s1>>>();
    gemm_out_kernel<<<dim3(8, 8, 1), 256, 0, s1>>>(wd, bd, out);
    cudaEventRecord(g_ss.ed, s1);

    // main: big attn write
    attn_write_kernel<<<dim3(SL, NH, BS), 256>>>(attn);

    // join
    cudaStreamWaitEvent(0, g_ss.ed, 0);
}

// round 11
// speedup vs baseline: 1.3470x; 1.0108x over previous
#include <cuda_runtime.h>
#include <cstdint>

#define BS 4
#define SL 128
#define DM 512
#define NH 8
#define DP 64

typedef unsigned long long u64;

// ---------------- scratch (device globals; no allocation allowed) ----------------
__device__ int   g_idx[3][SL][SL];        // 0:q 1:k 2:v permutations
__device__ float g_qp[BS*SL*DM];
__device__ float g_kp[BS*SL*DM];
__device__ float g_vp[BS*SL*DM];
__device__ float g_P [BS*NH*SL*SL];       // exp(G - rowmax)
__device__ float g_R [BS*NH*SL*SL];       // 1 / prefix-sum
__device__ float g_eff[BS*SL*DM];

// ---- side stream + events (host objects, created at static-init) ----
struct SideStream {
    cudaStream_t s1;
    cudaEvent_t eg, ed;
    SideStream() {
        cudaStreamCreateWithFlags(&s1, cudaStreamNonBlocking);
        cudaEventCreateWithFlags(&eg, cudaEventDisableTiming);
        cudaEventCreateWithFlags(&ed, cudaEventDisableTiming);
    }
};
static SideStream g_ss;

// ---------------- packed fp32x2 helpers (sm_103a FFMA2) ----------------
__device__ __forceinline__ u64 pk2(float lo, float hi) {
    u64 r; asm("mov.b64 %0, {%1,%2};" : "=l"(r) : "f"(lo), "f"(hi)); return r;
}
__device__ __forceinline__ void upk2(u64 v, float& lo, float& hi) {
    asm("mov.b64 {%0,%1}, %2;" : "=f"(lo), "=f"(hi) : "l"(v));
}
__device__ __forceinline__ u64 ffma2(u64 a, u64 b, u64 c) {
    u64 d; asm("fma.rn.f32x2 %0, %1, %2, %3;" : "=l"(d) : "l"(a), "l"(b), "l"(c)); return d;
}

// ---------------- threefry2x32 (JAX-compatible) ----------------
__device__ __forceinline__ uint2 tf2x32(uint32_t k0, uint32_t k1, uint32_t x0, uint32_t x1) {
    uint32_t k2 = k0 ^ k1 ^ 0x1BD11BDAu;
    x0 += k0; x1 += k1;
#define TFR(R) { x0 += x1; x1 = (x1 << R) | (x1 >> (32 - R)); x1 ^= x0; }
    TFR(13) TFR(15) TFR(26) TFR(6)
    x0 += k1; x1 += k2 + 1u;
    TFR(17) TFR(29) TFR(16) TFR(24)
    x0 += k2; x1 += k0 + 2u;
    TFR(13) TFR(15) TFR(26) TFR(6)
    x0 += k0; x1 += k1 + 3u;
    TFR(17) TFR(29) TFR(16) TFR(24)
    x0 += k1; x1 += k2 + 4u;
    TFR(13) TFR(15) TFR(26) TFR(6)
    x0 += k2; x1 += k0 + 5u;
#undef TFR
    return make_uint2(x0, x1);
}

// ---------------- 512x512x512 GEMM body (FFMA2 packed): C = A@B + bias --------
__device__ __forceinline__ void gemm512_body(const float* __restrict__ A,
                                             const float* __restrict__ B,
                                             const float* __restrict__ bias,
                                             float* __restrict__ C,
                                             float As[16][68], float Bs[16][68]) {
    int tid = threadIdx.x;
    int bm = blockIdx.y << 6, bn = blockIdx.x << 6;
    int tr = tid >> 4, tc = tid & 15;
    u64 acc2[4][2];
    #pragma unroll
    for (int i = 0; i < 4; i++) { acc2[i][0] = 0ull; acc2[i][1] = 0ull; }

    int lm = tid >> 2, lkq = (tid & 3) << 2;
    int lk = tid >> 4, lnq = (tid & 15) << 2;

    float4 a  = *(const float4*)&A[(bm + lm) * 512 + lkq];
    float4 bb = *(const float4*)&B[lk * 512 + bn + lnq];

    for (int k0 = 0; k0 < 512; k0 += 16) {
        As[lkq + 0][lm] = a.x; As[lkq + 1][lm] = a.y;
        As[lkq + 2][lm] = a.z; As[lkq + 3][lm] = a.w;
        *(float4*)&Bs[lk][lnq] = bb;
        __syncthreads();
        if (k0 + 16 < 512) {
            a  = *(const float4*)&A[(bm + lm) * 512 + k0 + 16 + lkq];
            bb = *(const float4*)&B[(k0 + 16 + lk) * 512 + bn + lnq];
        }
        #pragma unroll
        for (int kk = 0; kk < 16; kk++) {
            float4 av = *(float4*)&As[kk][tr << 2];
            float4 bv = *(float4*)&Bs[kk][tc << 2];
            u64 b01 = pk2(bv.x, bv.y), b23 = pk2(bv.z, bv.w);
            u64 ad;
            ad = pk2(av.x, av.x);
            acc2[0][0] = ffma2(ad, b01, acc2[0][0]);
            acc2[0][1] = ffma2(ad, b23, acc2[0][1]);
            ad = pk2(av.y, av.y);
            acc2[1][0] = ffma2(ad, b01, acc2[1][0]);
            acc2[1][1] = ffma2(ad, b23, acc2[1][1]);
            ad = pk2(av.z, av.z);
            acc2[2][0] = ffma2(ad, b01, acc2[2][0]);
            acc2[2][1] = ffma2(ad, b23, acc2[2][1]);
            ad = pk2(av.w, av.w);
            acc2[3][0] = ffma2(ad, b01, acc2[3][0]);
            acc2[3][1] = ffma2(ad, b23, acc2[3][1]);
        }
        __syncthreads();
    }
    float4 bsv = *(const float4*)&bias[bn + (tc << 2)];
    #pragma unroll
    for (int i = 0; i < 4; i++) {
        float4 o;
        upk2(acc2[i][0], o.x, o.y);
        upk2(acc2[i][1], o.z, o.w);
        o.x += bsv.x; o.y += bsv.y; o.z += bsv.z; o.w += bsv.w;
        *(float4*)&C[(bm + (tr << 2) + i) * 512 + bn + (tc << 2)] = o;
    }
}

// ---------------- fused: q/k/v projections (z=0..2) + all 3 perms (z=3) --------
// grid (8,8,4), block 256
__global__ void fused_proj_perm_kernel(
        const float* __restrict__ q, const float* __restrict__ k,
        const float* __restrict__ v,
        const float* __restrict__ wq, const float* __restrict__ wk,
        const float* __restrict__ wv,
        const float* __restrict__ bq, const float* __restrict__ bk,
        const float* __restrict__ bv) {
    __shared__ float As[16][68], Bs[16][68];
    __shared__ float keys[2][SL];
    int z = blockIdx.z;
    if (z < 3) {
        const float *A, *B, *bias; float* C;
        if (z == 0)      { A = q; B = wq; bias = bq; C = g_qp; }
        else if (z == 1) { A = k; B = wk; bias = bk; C = g_kp; }
        else             { A = v; B = wv; bias = bv; C = g_vp; }
        gemm512_body(A, B, bias, C, As, Bs);
        return;
    }
    int id = blockIdx.y * 8 + blockIdx.x;        // 0..63
    int tid = threadIdx.x;
    int half = tid >> 7, j = tid & 127;
    int t = id * 2 + half;                       // 0..127
    for (int p = 0; p < 3; p++) {
        uint2 fk = tf2x32(0u, 42u, 0u, (uint32_t)p);
        float key;
        if (j < t) {
            uint32_t i = (uint32_t)(t * SL + j);
            uint2 r = tf2x32(fk.x, fk.y, 0u, i);
            uint32_t bits = r.x ^ r.y;
            key = __uint_as_float((bits >> 9) | 0x3f800000u) - 1.0f;
        } else {
            key = (float)j + 2.0f;
        }
        keys[half][j] = key;
        __syncthreads();
        int rank = 0;
        #pragma unroll 8
        for (int jj = 0; jj < SL; jj++) {
            float o = keys[half][jj];
            rank += (o < key) || (o == key && jj < j);
        }
        g_idx[p][t][rank] = j;
        __syncthreads();
    }
}

// ---------------- final dense, WIDE: 32x64 tiles, grid (8,16) = 128 blocks ------
__global__ void __launch_bounds__(256) gemm_out_kernel(
        const float* __restrict__ wd, const float* __restrict__ bd,
        float* __restrict__ out) {
    __shared__ float As[16][36];   // [k][m], m-tile 32 (+pad)
    __shared__ float Bs[16][68];   // [k][n], n-tile 64
    const float* A = g_eff;
    int tid = threadIdx.x;
    int bm = blockIdx.y << 5, bn = blockIdx.x << 6;
    int tr = tid >> 4, tc = tid & 15;
    u64 acc2[2][2];
    acc2[0][0] = acc2[0][1] = acc2[1][0] = acc2[1][1] = 0ull;

    int lm = tid >> 2, lkq = (tid & 3) << 2;   // A loader (threads 0..127)
    int lk = tid >> 4, lnq = (tid & 15) << 2;  // B loader
    bool loadA = (tid < 128);

    float4 a = make_float4(0.f, 0.f, 0.f, 0.f);
    if (loadA) a = *(const float4*)&A[(bm + lm) * 512 + lkq];
    float4 bb = *(const float4*)&wd[lk * 512 + bn + lnq];

    for (int k0 = 0; k0 < 512; k0 += 16) {
        if (loadA) {
            As[lkq + 0][lm] = a.x; As[lkq + 1][lm] = a.y;
            As[lkq + 2][lm] = a.z; As[lkq + 3][lm] = a.w;
        }
        *(float4*)&Bs[lk][lnq] = bb;
        __syncthreads();
        if (k0 + 16 < 512) {
            if (loadA) a = *(const float4*)&A[(bm + lm) * 512 + k0 + 16 + lkq];
            bb = *(const float4*)&wd[(k0 + 16 + lk) * 512 + bn + lnq];
        }
        #pragma unroll
        for (int kk = 0; kk < 16; kk++) {
            float a0 = As[kk][tr << 1], a1 = As[kk][(tr << 1) + 1];
            float4 bv = *(float4*)&Bs[kk][tc << 2];
            u64 b01 = pk2(bv.x, bv.y), b23 = pk2(bv.z, bv.w);
            u64 ad;
            ad = pk2(a0, a0);
            acc2[0][0] = ffma2(ad, b01, acc2[0][0]);
            acc2[0][1] = ffma2(ad, b23, acc2[0][1]);
            ad = pk2(a1, a1);
            acc2[1][0] = ffma2(ad, b01, acc2[1][0]);
            acc2[1][1] = ffma2(ad, b23, acc2[1][1]);
        }
        __syncthreads();
    }
    float4 bsv = *(const float4*)&bd[bn + (tc << 2)];
    #pragma unroll
    for (int i = 0; i < 2; i++) {
        float4 o;
        upk2(acc2[i][0], o.x, o.y);
        upk2(acc2[i][1], o.z, o.w);
        o.x += bsv.x; o.y += bsv.y; o.z += bsv.z; o.w += bsv.w;
        *(float4*)&out[(bm + (tr << 1) + i) * 512 + bn + (tc << 2)] = o;
    }
}

// ---------------- G = Q K^T /8 per (b,h); P = exp(G-max); R = 1/prefix-sum ------
__global__ void gp_kernel() {
    __shared__ float ksT[64][129];    // [d][j]
    __shared__ float Gs[8][128];
    int rc = blockIdx.x, h = blockIdx.y, b = blockIdx.z;
    int i0 = rc << 3;
    int tid = threadIdx.x;
    int j = tid & 127;
    int ihalf = tid >> 7;

    #pragma unroll
    for (int u = 0; u < 8; u++) {
        int lin = tid + u * 256;
        int j2 = lin >> 4;
        int dq = (lin & 15) << 2;
        float4 kv = *(const float4*)&g_kp[((b * SL + j2) << 9) + (h << 6) + dq];
        ksT[dq + 0][j2] = kv.x;
        ksT[dq + 1][j2] = kv.y;
        ksT[dq + 2][j2] = kv.z;
        ksT[dq + 3][j2] = kv.w;
    }
    __syncthreads();

    float acc[4];
    #pragma unroll
    for (int r = 0; r < 4; r++) acc[r] = 0.f;
    const float* qbase = g_qp + ((b * SL + i0) << 9) + (h << 6);
    #pragma unroll
    for (int d4 = 0; d4 < 16; d4++) {
        float k0v = ksT[(d4 << 2) + 0][j];
        float k1v = ksT[(d4 << 2) + 1][j];
        float k2v = ksT[(d4 << 2) + 2][j];
        float k3v = ksT[(d4 << 2) + 3][j];
        #pragma unroll
        for (int r = 0; r < 4; r++) {
            float4 qv = __ldg((const float4*)&qbase[(((ihalf << 2) + r) << 9) + (d4 << 2)]);
            acc[r] += qv.x * k0v + qv.y * k1v + qv.z * k2v + qv.w * k3v;
        }
    }
    #pragma unroll
    for (int r = 0; r < 4; r++) Gs[(ihalf << 2) + r][j] = acc[r] * 0.125f;
    __syncthreads();

    int w = tid >> 5, lane = tid & 31;
    {
        int i = w;
        float4 g = *(float4*)&Gs[i][lane << 2];
        float m = fmaxf(fmaxf(g.x, g.y), fmaxf(g.z, g.w));
        #pragma unroll
        for (int off = 16; off; off >>= 1) m = fmaxf(m, __shfl_xor_sync(0xffffffffu, m, off));
        float e0 = __expf(g.x - m), e1 = __expf(g.y - m);
        float e2 = __expf(g.z - m), e3 = __expf(g.w - m);
        int rowbase = ((b * NH + h) * SL + i0 + i) * SL;
        *(float4*)&g_P[rowbase + (lane << 2)] = make_float4(e0, e1, e2, e3);
        float s1 = e0 + e1, s2 = s1 + e2, s3 = s2 + e3;
        float tot = s3, sc = tot;
        #pragma unroll
        for (int off = 1; off < 32; off <<= 1) {
            float o = __shfl_up_sync(0xffffffffu, sc, off);
            if (lane >= off) sc += o;
        }
        float excl = sc - tot;
        *(float4*)&g_R[rowbase + (lane << 2)] =
            make_float4(1.0f / (excl + e0), 1.0f / (excl + s1),
                        1.0f / (excl + s2), 1.0f / (excl + s3));
    }
}

// ---------------- big writer: attn[b,t,h,q,k] (256 MB) ----------------
__global__ void __launch_bounds__(256, 6) attn_write_kernel(float* __restrict__ attn) {
    int t = blockIdx.x, h = blockIdx.y, b = blockIdx.z;
    __shared__ int idxk_s[SL];
    __shared__ int idxq_s[SL];
    __shared__ float pbuf[8][2][SL];
    int tid = threadIdx.x;
    if (tid < SL) {
        idxk_s[tid] = g_idx[1][t][tid];
        idxq_s[tid] = g_idx[0][t][tid];
    }
    __syncthreads();
    float uval = 1.0f / (float)(t + 1);
    float* base = attn + (((size_t)((b * SL + t) * NH + h)) << 14);
    const float* Pbh = g_P + ((size_t)(b * NH + h) << 14);
    const float* Rbh = g_R + ((size_t)(b * NH + h) << 14);
    int lane = tid & 31, w = tid >> 5;
    int k0 = lane << 2;
    int  j0 = idxk_s[k0], j1 = idxk_s[k0 + 1], j2 = idxk_s[k0 + 2], j3 = idxk_s[k0 + 3];
    bool p0 = (k0 <= t), p1 = (k0 + 1 <= t), p2 = (k0 + 2 <= t), p3 = (k0 + 3 <= t);

    for (int qq = w; qq <= t; qq += 16) {
        int q2 = qq + 8;
        bool have2 = (q2 <= t);
        int iq0 = idxq_s[qq];
        float r0 = __ldg(&Rbh[iq0 * SL + t]);
        float4 P0 = __ldg((const float4*)&Pbh[iq0 * SL + k0]);
        float r1 = 0.f; float4 P1;
        if (have2) {
            int iq1 = idxq_s[q2];
            r1 = __ldg(&Rbh[iq1 * SL + t]);
            P1 = __ldg((const float4*)&Pbh[iq1 * SL + k0]);
        }
        *(float4*)&pbuf[w][0][k0] = P0;
        if (have2) *(float4*)&pbuf[w][1][k0] = P1;
        __syncwarp();
        const float* pa = pbuf[w][0];
        float4 v0;
        v0.x = p0 ? pa[j0] * r0 : 0.f;
        v0.y = p1 ? pa[j1] * r0 : 0.f;
        v0.z = p2 ? pa[j2] * r0 : 0.f;
        v0.w = p3 ? pa[j3] * r0 : 0.f;
        __stcs((float4*)&base[qq * SL + k0], v0);
        if (have2) {
            const float* pb = pbuf[w][1];
            float4 v1;
            v1.x = p0 ? pb[j0] * r1 : 0.f;
            v1.y = p1 ? pb[j1] * r1 : 0.f;
            v1.z = p2 ? pb[j2] * r1 : 0.f;
            v1.w = p3 ? pb[j3] * r1 : 0.f;
            __stcs((float4*)&base[q2 * SL + k0], v1);
        }
        __syncwarp();
    }
    float4 uv;
    uv.x = p0 ? uval : 0.f;
    uv.y = p1 ? uval : 0.f;
    uv.z = p2 ? uval : 0.f;
    uv.w = p3 ? uval : 0.f;
    int u0 = (w > t) ? w : (w + ((t - w) / 8 + 1) * 8);
    for (int q2 = u0; q2 < SL; q2 += 8) {
        __stcs((float4*)&base[q2 * SL + k0], uv);
    }
}

// ---------------- eff[b,t,:] = diag ctx row, permutation-inverted ----------------
__global__ void eff_kernel() {
    int t = blockIdx.x, b = blockIdx.y;
    int tid = threadIdx.x;
    __shared__ int inv_s[SL];
    __shared__ float ws[NH][SL];
    if (tid < SL) inv_s[g_idx[2][t][tid]] = tid;
    __syncthreads();
    for (int idx = tid; idx < NH * SL; idx += 256) {
        int h = idx >> 7, j = idx & 127;
        int k = inv_s[j];
        float val = 0.f;
        if (k <= t) {
            int jj = g_idx[1][t][k];
            int rb = ((b * NH + h) * SL + t) * SL;
            val = g_P[rb + jj] * g_R[rb + t];
        }
        ws[h][j] = val;
    }
    __syncthreads();
    int h0 = tid >> 6;
    int c1 = tid + 256, h1 = c1 >> 6;
    const float* Vb = g_vp + ((size_t)(b * SL) << 9);
    float a0 = 0.f, a1 = 0.f, b0 = 0.f, b1 = 0.f;
    float c0a = 0.f, c1a = 0.f, d0a = 0.f, d1a = 0.f;
    int j = 0;
    for (; j + 3 <= t; j += 4) {
        const float* r0 = Vb + ((size_t)(j    ) << 9);
        const float* r1 = Vb + ((size_t)(j + 1) << 9);
        const float* r2 = Vb + ((size_t)(j + 2) << 9);
        const float* r3 = Vb + ((size_t)(j + 3) << 9);
        a0  += ws[h0][j    ] * __ldg(&r0[tid]);
        a1  += ws[h1][j    ] * __ldg(&r0[c1]);
        b0  += ws[h0][j + 1] * __ldg(&r1[tid]);
        b1  += ws[h1][j + 1] * __ldg(&r1[c1]);
        c0a += ws[h0][j + 2] * __ldg(&r2[tid]);
        c1a += ws[h1][j + 2] * __ldg(&r2[c1]);
        d0a += ws[h0][j + 3] * __ldg(&r3[tid]);
        d1a += ws[h1][j + 3] * __ldg(&r3[c1]);
    }
    for (; j <= t; j++) {
        const float* r0 = Vb + ((size_t)j << 9);
        a0 += ws[h0][j] * __ldg(&r0[tid]);
        a1 += ws[h1][j] * __ldg(&r0[c1]);
    }
    size_t ob = (size_t)(b * SL + t) << 9;
    g_eff[ob + tid] = (a0 + b0) + (c0a + d0a);
    g_eff[ob + c1]  = (a1 + b1) + (c1a + d1a);
}

// ---------------- launch: 5 kernel nodes ----------------
extern "C" void kernel_launch(void* const* d_in, const int* in_sizes, int n_in,
                              void* d_out, int out_size) {
    const float* q  = (const float*)d_in[0];
    const float* k  = (const float*)d_in[1];
    const float* v  = (const float*)d_in[2];
    const float* wq = (const float*)d_in[4];
    const float* bq = (const float*)d_in[5];
    const float* wk = (const float*)d_in[6];
    const float* bk = (const float*)d_in[7];
    const float* wv = (const float*)d_in[8];
    const float* bv = (const float*)d_in[9];
    const float* wd = (const float*)d_in[10];
    const float* bd = (const float*)d_in[11];

    float* out  = (float*)d_out;                 // (BS,SL,DM)
    float* attn = out + (size_t)BS * SL * DM;    // (BS,SL,NH,SL,SL)

    cudaStream_t s1 = g_ss.s1;

    fused_proj_perm_kernel<<<dim3(8, 8, 4), 256>>>(q, k, v, wq, wk, wv, bq, bk, bv);
    gp_kernel<<<dim3(16, NH, BS), 256>>>();
    cudaEventRecord(g_ss.eg, 0);

    cudaStreamWaitEvent(s1, g_ss.eg, 0);
    eff_kernel<<<dim3(SL, BS), 256, 0, s1>>>();
    gemm_out_kernel<<<dim3(8, 16, 1), 256, 0, s1>>>(wd, bd, out);
    cudaEventRecord(g_ss.ed, s1);

    attn_write_kernel<<<dim3(SL, NH, BS), 256>>>(attn);

    cudaStreamWaitEvent(0, g_ss.ed, 0);
}